// round 1
// baseline (speedup 1.0000x reference)
#include <cuda_runtime.h>

#define NB 8192   // rows of x
#define NP 8192   // rows of prototypes
#define NF 256    // feature dim

// Precomputed squared norms (allocation-free scratch).
__device__ float g_xsq[NB];
__device__ float g_psq[NP];

// One block per row (first NB blocks: x, next NP blocks: prototypes).
// 256 threads, one element each, tree reduce.
__global__ __launch_bounds__(256) void norms_kernel(const float* __restrict__ X,
                                                    const float* __restrict__ Pr) {
    int row = blockIdx.x;
    const float* src;
    float* dst;
    if (row < NB) {
        src = X + (size_t)row * NF;
        dst = g_xsq + row;
    } else {
        src = Pr + (size_t)(row - NB) * NF;
        dst = g_psq + (row - NB);
    }
    int lane = threadIdx.x;
    float v = src[lane];
    float s = v * v;
    #pragma unroll
    for (int o = 16; o > 0; o >>= 1) s += __shfl_xor_sync(0xffffffffu, s, o);
    __shared__ float red[8];
    if ((lane & 31) == 0) red[lane >> 5] = s;
    __syncthreads();
    if (lane == 0) {
        float t = 0.f;
        #pragma unroll
        for (int i = 0; i < 8; i++) t += red[i];
        *dst = t;
    }
}

// 128x128 tile, BK=8, 256 threads, 8x8 per thread.
// out[b,p] = exp(-sqrt(max(xsq[b]+psq[p]-2*dot(x_b,p_p),0)) * 0.5)
__global__ __launch_bounds__(256) void gauss_gemm_kernel(const float* __restrict__ X,
                                                         const float* __restrict__ Pr,
                                                         float* __restrict__ out) {
    constexpr int BM = 128, BN = 128, BK = 8, TM = 8, TN = 8;

    __shared__ float As[BK][BM];
    __shared__ float Bs[BK][BN];

    const int bm = blockIdx.y * BM;
    const int bn = blockIdx.x * BN;
    const int tid = threadIdx.x;
    const int tx = tid & 15;    // 0..15 -> N
    const int ty = tid >> 4;    // 0..15 -> M

    // Global-load mapping: each thread loads one float4 per tile per matrix.
    const int loadRow = tid >> 1;         // 0..127
    const int loadCol = (tid & 1) * 4;    // 0 or 4

    const float* xg = X + (size_t)(bm + loadRow) * NF + loadCol;
    const float* pg = Pr + (size_t)(bn + loadRow) * NF + loadCol;

    float acc[TM][TN];
    #pragma unroll
    for (int i = 0; i < TM; i++)
        #pragma unroll
        for (int j = 0; j < TN; j++) acc[i][j] = 0.f;

    for (int k = 0; k < NF; k += BK) {
        float4 a = *reinterpret_cast<const float4*>(xg + k);
        float4 b = *reinterpret_cast<const float4*>(pg + k);
        As[loadCol + 0][loadRow] = a.x;
        As[loadCol + 1][loadRow] = a.y;
        As[loadCol + 2][loadRow] = a.z;
        As[loadCol + 3][loadRow] = a.w;
        Bs[loadCol + 0][loadRow] = b.x;
        Bs[loadCol + 1][loadRow] = b.y;
        Bs[loadCol + 2][loadRow] = b.z;
        Bs[loadCol + 3][loadRow] = b.w;
        __syncthreads();

        #pragma unroll
        for (int kk = 0; kk < BK; kk++) {
            float ar[TM], br[TN];
            #pragma unroll
            for (int i = 0; i < TM; i += 4) {
                float4 v = *reinterpret_cast<const float4*>(&As[kk][ty * TM + i]);
                ar[i + 0] = v.x; ar[i + 1] = v.y; ar[i + 2] = v.z; ar[i + 3] = v.w;
            }
            #pragma unroll
            for (int j = 0; j < TN; j += 4) {
                float4 v = *reinterpret_cast<const float4*>(&Bs[kk][tx * TN + j]);
                br[j + 0] = v.x; br[j + 1] = v.y; br[j + 2] = v.z; br[j + 3] = v.w;
            }
            #pragma unroll
            for (int i = 0; i < TM; i++)
                #pragma unroll
                for (int j = 0; j < TN; j++)
                    acc[i][j] = fmaf(ar[i], br[j], acc[i][j]);
        }
        __syncthreads();
    }

    // Epilogue: combine norms, sqrt, exp, vectorized store.
    float xs[TM], ps[TN];
    #pragma unroll
    for (int i = 0; i < TM; i++) xs[i] = g_xsq[bm + ty * TM + i];
    #pragma unroll
    for (int j = 0; j < TN; j++) ps[j] = g_psq[bn + tx * TN + j];

    #pragma unroll
    for (int i = 0; i < TM; i++) {
        float4 r0, r1;
        float* rr0 = &r0.x;
        float* rr1 = &r1.x;
        #pragma unroll
        for (int j = 0; j < TN; j++) {
            float d2 = fmaxf(xs[i] + ps[j] - 2.0f * acc[i][j], 0.0f);
            float val = __expf(-0.5f * sqrtf(d2));
            if (j < 4) rr0[j] = val; else rr1[j - 4] = val;
        }
        size_t orow = (size_t)(bm + ty * TM + i) * NP + bn + tx * TN;
        *reinterpret_cast<float4*>(out + orow)     = r0;
        *reinterpret_cast<float4*>(out + orow + 4) = r1;
    }
}

extern "C" void kernel_launch(void* const* d_in, const int* in_sizes, int n_in,
                              void* d_out, int out_size) {
    const float* x = (const float*)d_in[0];   // [8192, 256]
    const float* p = (const float*)d_in[1];   // [8192, 256]
    float* out = (float*)d_out;               // [8192, 8192]

    norms_kernel<<<NB + NP, 256>>>(x, p);

    dim3 grid(NP / 128, NB / 128);
    gauss_gemm_kernel<<<grid, 256>>>(x, p, out);
}

// round 3
// speedup vs baseline: 2.5808x; 2.5808x over previous
#include <cuda_runtime.h>
#include <cstdint>

#define NB 8192
#define NP 8192
#define NF 256
#define BM 128
#define BN 128
#define BK 16
#define STAGES 3
#define KT (NF / BK)              // 16 k-tiles
#define ASTR 20                   // padded floats per smem row (80B, 16B-aligned, conflict-free)
#define STAGE_FLOATS (BM * ASTR)  // 2560
#define SMEM_BYTES (STAGES * 2 * STAGE_FLOATS * 4)  // 61440

// ---------------- device scratch (allocation-free) ----------------
__device__ float g_xsq[NB];
__device__ float g_psq[NP];
__device__ float g_Xr[(size_t)NB * NF];   // tf32-rounded x
__device__ float g_Pr[(size_t)NP * NF];   // tf32-rounded prototypes

__device__ __forceinline__ uint32_t smem_u32(const void* p) {
    uint32_t a;
    asm("{ .reg .u64 t; cvta.to.shared.u64 t, %1; cvt.u32.u64 %0, t; }" : "=r"(a) : "l"(p));
    return a;
}

// ---------------- prepass: tf32 rounding + row norms ----------------
__global__ __launch_bounds__(256) void prep_kernel(const float* __restrict__ X,
                                                   const float* __restrict__ P) {
    int row = blockIdx.x;
    bool isP = row >= NB;
    int r = isP ? row - NB : row;
    const float* src = (isP ? P : X) + (size_t)r * NF;
    float* dst = (isP ? g_Pr : g_Xr) + (size_t)r * NF;

    int t = threadIdx.x;
    float v = src[t];
    uint32_t u;
    asm("cvt.rna.tf32.f32 %0, %1;" : "=r"(u) : "f"(v));
    dst[t] = __uint_as_float(u);

    float s = v * v;
    #pragma unroll
    for (int o = 16; o > 0; o >>= 1) s += __shfl_xor_sync(0xffffffffu, s, o);
    __shared__ float red[8];
    if ((t & 31) == 0) red[t >> 5] = s;
    __syncthreads();
    if (t == 0) {
        float tot = 0.f;
        #pragma unroll
        for (int i = 0; i < 8; i++) tot += red[i];
        (isP ? g_psq : g_xsq)[r] = tot;
    }
}

// ---------------- main kernel: tf32 mma.sync GEMM + fused epilogue ----------------
__global__ __launch_bounds__(256, 2) void gauss_mma_kernel(float* __restrict__ out) {
    extern __shared__ float sm[];
    float* As = sm;                            // [STAGES][128][ASTR]
    float* Bs = sm + STAGES * STAGE_FLOATS;    // [STAGES][128][ASTR]

    const int bm = blockIdx.y * BM;
    const int bn = blockIdx.x * BN;
    const int tid = threadIdx.x;
    const int w = tid >> 5, lane = tid & 31;
    const int wm = w & 1, wn = w >> 1;     // warp grid 2(M) x 4(N); warp tile 64x32
    const int g = lane >> 2, tg = lane & 3;

    // global->smem loader mapping: each thread copies 2x16B for A and for B per stage
    const int lrow = tid >> 1;             // 0..127
    const int lcol = (tid & 1) * 8;        // 0 or 8
    const float* gA = g_Xr + (size_t)(bm + lrow) * NF + lcol;
    const float* gB = g_Pr + (size_t)(bn + lrow) * NF + lcol;
    const uint32_t sA = smem_u32(&As[lrow * ASTR + lcol]);
    const uint32_t sB = smem_u32(&Bs[lrow * ASTR + lcol]);

    auto issue = [&](int kt) {
        const uint32_t so = (uint32_t)(kt % STAGES) * (STAGE_FLOATS * 4);
        const float* a = gA + kt * BK;
        const float* b = gB + kt * BK;
        asm volatile("cp.async.cg.shared.global [%0], [%1], 16;" :: "r"(sA + so), "l"(a));
        asm volatile("cp.async.cg.shared.global [%0], [%1], 16;" :: "r"(sA + so + 16), "l"(a + 4));
        asm volatile("cp.async.cg.shared.global [%0], [%1], 16;" :: "r"(sB + so), "l"(b));
        asm volatile("cp.async.cg.shared.global [%0], [%1], 16;" :: "r"(sB + so + 16), "l"(b + 4));
        asm volatile("cp.async.commit_group;" ::: "memory");
    };

    // fragment base pointers (stage 0)
    const uint32_t* aF = reinterpret_cast<const uint32_t*>(As) + (wm * 64 + g) * ASTR + tg;
    const uint32_t* bF = reinterpret_cast<const uint32_t*>(Bs) + (wn * 32 + g) * ASTR + tg;

    float acc[4][4][4];
    #pragma unroll
    for (int mt = 0; mt < 4; mt++)
        #pragma unroll
        for (int nt = 0; nt < 4; nt++)
            #pragma unroll
            for (int q = 0; q < 4; q++) acc[mt][nt][q] = 0.f;

    issue(0);
    issue(1);

    for (int kt = 0; kt < KT; kt++) {
        asm volatile("cp.async.wait_group 1;" ::: "memory");
        __syncthreads();
        if (kt + 2 < KT) issue(kt + 2);

        const int sbase = (kt % STAGES) * STAGE_FLOATS;
        #pragma unroll
        for (int kk = 0; kk < 2; kk++) {
            uint32_t a[4][4], b[4][2];
            #pragma unroll
            for (int mt = 0; mt < 4; mt++) {
                const uint32_t* p = aF + sbase + mt * (16 * ASTR) + kk * 8;
                a[mt][0] = p[0];
                a[mt][1] = p[8 * ASTR];
                a[mt][2] = p[4];
                a[mt][3] = p[8 * ASTR + 4];
            }
            #pragma unroll
            for (int nt = 0; nt < 4; nt++) {
                const uint32_t* p = bF + sbase + nt * (8 * ASTR) + kk * 8;
                b[nt][0] = p[0];
                b[nt][1] = p[4];
            }
            #pragma unroll
            for (int mt = 0; mt < 4; mt++)
                #pragma unroll
                for (int nt = 0; nt < 4; nt++)
                    asm volatile(
                        "mma.sync.aligned.m16n8k8.row.col.f32.tf32.tf32.f32 "
                        "{%0,%1,%2,%3}, {%4,%5,%6,%7}, {%8,%9}, {%0,%1,%2,%3};"
                        : "+f"(acc[mt][nt][0]), "+f"(acc[mt][nt][1]),
                          "+f"(acc[mt][nt][2]), "+f"(acc[mt][nt][3])
                        : "r"(a[mt][0]), "r"(a[mt][1]), "r"(a[mt][2]), "r"(a[mt][3]),
                          "r"(b[nt][0]), "r"(b[nt][1]));
        }
    }

    // ---------------- fused epilogue ----------------
    const int orow0 = bm + wm * 64 + g;
    const int ocol0 = bn + wn * 32 + 2 * tg;

    #pragma unroll
    for (int mt = 0; mt < 4; mt++) {
        const int r0 = orow0 + mt * 16;
        const float xs0 = g_xsq[r0];
        const float xs1 = g_xsq[r0 + 8];
        float* orow_a = out + (size_t)r0 * NP;
        float* orow_b = out + (size_t)(r0 + 8) * NP;
        #pragma unroll
        for (int nt = 0; nt < 4; nt++) {
            const int c = ocol0 + nt * 8;
            const float p0 = g_psq[c];
            const float p1 = g_psq[c + 1];
            float d00 = fmaxf(fmaf(-2.f, acc[mt][nt][0], xs0 + p0), 0.f);
            float d01 = fmaxf(fmaf(-2.f, acc[mt][nt][1], xs0 + p1), 0.f);
            float d10 = fmaxf(fmaf(-2.f, acc[mt][nt][2], xs1 + p0), 0.f);
            float d11 = fmaxf(fmaf(-2.f, acc[mt][nt][3], xs1 + p1), 0.f);
            float2 v0 = make_float2(__expf(-0.5f * sqrtf(d00)), __expf(-0.5f * sqrtf(d01)));
            float2 v1 = make_float2(__expf(-0.5f * sqrtf(d10)), __expf(-0.5f * sqrtf(d11)));
            *reinterpret_cast<float2*>(orow_a + c) = v0;
            *reinterpret_cast<float2*>(orow_b + c) = v1;
        }
    }
}

// ---------------- launch ----------------
extern "C" void kernel_launch(void* const* d_in, const int* in_sizes, int n_in,
                              void* d_out, int out_size) {
    const float* x = (const float*)d_in[0];   // [8192, 256]
    const float* p = (const float*)d_in[1];   // [8192, 256]
    float* out = (float*)d_out;               // [8192, 8192]

    static bool configured = false;
    if (!configured) {
        cudaFuncSetAttribute(gauss_mma_kernel,
                             cudaFuncAttributeMaxDynamicSharedMemorySize, SMEM_BYTES);
        configured = true;
    }

    prep_kernel<<<NB + NP, 256>>>(x, p);

    dim3 grid(NP / BN, NB / BM);
    gauss_mma_kernel<<<grid, 256, SMEM_BYTES>>>(out);
}

// round 5
// speedup vs baseline: 2.9722x; 1.1516x over previous
#include <cuda_runtime.h>
#include <cstdint>

#define NB 8192
#define NP 8192
#define NF 256
#define BM 128
#define BN 128
#define BK 32
#define KT (NF / BK)        // 8 k-tiles
#define STAGES 3
#define AKB 16384           // bytes of one 128x32 fp32 block (A or B)
#define STAGE_B (2 * AKB)   // 32 KB per stage (A + B)
#define SMEM_BYTES (STAGES * STAGE_B)  // 96 KB

// ---------------- device scratch (allocation-free) ----------------
__device__ float g_xsq[NB];
__device__ float g_psq[NP];
// fragment-order permuted tf32 copies: [tile(64)][kblock(8)][16KB block]
__device__ __align__(1024) float g_Xr[(size_t)NB * NF];
__device__ __align__(1024) float g_Pr[(size_t)NP * NF];

__device__ __forceinline__ uint32_t smem_u32(const void* p) {
    uint32_t a;
    asm("{ .reg .u64 t; cvta.to.shared.u64 t, %1; cvt.u32.u64 %0, t; }" : "=r"(a) : "l"(p));
    return a;
}

// ---------------- prepass: tf32 round + permute + row norms ----------------
// A block (128 rows x 32 k, 16KB): atom = 16 rows x 8 k = 512B, idx = ak*8+am (32 atoms)
//   within atom: lane=(rr&7)*4+(cc&3), q=(rr>>3)|((cc>>2)<<1), off=lane*16+q*4
// B block (128 n x 32 k, 16KB): atom = 8 n x 8 k = 256B, idx = ak*16+an (64 atoms)
//   within atom: lane=nn*4+(cc&3), q=cc>>2, off=lane*8+q*4
__global__ __launch_bounds__(256) void prep_kernel(const float* __restrict__ X,
                                                   const float* __restrict__ P) {
    int row = blockIdx.x;
    bool isP = row >= NB;
    int r = isP ? row - NB : row;
    int t = threadIdx.x;

    float v = (isP ? P : X)[(size_t)r * NF + t];
    uint32_t u;
    asm("cvt.rna.tf32.f32 %0, %1;" : "=r"(u) : "f"(v));

    int tile = r >> 7, rin = r & 127, kb = t >> 5, kin = t & 31;
    int ak = kin >> 3, cc = kin & 7;
    char* base = (char*)(isP ? g_Pr : g_Xr) + (((size_t)tile * 8 + kb) << 14);
    uint32_t off;
    if (!isP) {
        int am = rin >> 4, rr = rin & 15;
        off = ((uint32_t)(ak * 8 + am) << 9)
            + (uint32_t)((rr & 7) * 4 + (cc & 3)) * 16u
            + ((uint32_t)((rr >> 3) | ((cc >> 2) << 1)) << 2);
    } else {
        int an = rin >> 3, nn = rin & 7;
        off = ((uint32_t)(ak * 16 + an) << 8)
            + (uint32_t)(nn * 4 + (cc & 3)) * 8u
            + ((uint32_t)(cc >> 2) << 2);
    }
    *reinterpret_cast<float*>(base + off) = __uint_as_float(u);

    float s = v * v;
    #pragma unroll
    for (int o = 16; o > 0; o >>= 1) s += __shfl_xor_sync(0xffffffffu, s, o);
    __shared__ float red[8];
    if ((t & 31) == 0) red[t >> 5] = s;
    __syncthreads();
    if (t == 0) {
        float tot = 0.f;
        #pragma unroll
        for (int i = 0; i < 8; i++) tot += red[i];
        (isP ? g_psq : g_xsq)[r] = tot;
    }
}

// ---------------- main kernel ----------------
__global__ __launch_bounds__(256, 2) void gauss_mma_kernel(float* __restrict__ out) {
    extern __shared__ char sm[];
    const uint32_t sb = smem_u32(sm);

    // tile swizzle: groups of 64 tm x 16 tn for L2 reuse
    const int id = blockIdx.y * gridDim.x + blockIdx.x;
    const int tn = ((id >> 10) << 4) | (id & 15);
    const int tm = (id & 1023) >> 4;
    const int bm = tm * BM, bn = tn * BN;

    const int tid = threadIdx.x;
    const int w = tid >> 5, lane = tid & 31;
    const int wm = w & 1, wn = w >> 1;      // 2(M) x 4(N), warp tile 64x32
    const int g = lane >> 2, tg = lane & 3;

    const char* gA = (const char*)g_Xr + ((size_t)tm * 8 << 14);
    const char* gB = (const char*)g_Pr + ((size_t)tn * 8 << 14);

    auto issue = [&](int kt) {
        const uint32_t so = sb + (uint32_t)(kt % STAGES) * STAGE_B + (uint32_t)tid * 64;
        const char* a = gA + ((size_t)kt << 14) + tid * 64;
        const char* b = gB + ((size_t)kt << 14) + tid * 64;
        #pragma unroll
        for (int j = 0; j < 4; j++) {
            asm volatile("cp.async.cg.shared.global [%0], [%1], 16;" :: "r"(so + j * 16), "l"(a + j * 16));
            asm volatile("cp.async.cg.shared.global [%0], [%1], 16;" :: "r"(so + AKB + j * 16), "l"(b + j * 16));
        }
        asm volatile("cp.async.commit_group;" ::: "memory");
    };

    float acc[4][4][4];
    #pragma unroll
    for (int mt = 0; mt < 4; mt++)
        #pragma unroll
        for (int nt = 0; nt < 4; nt++)
            #pragma unroll
            for (int q = 0; q < 4; q++) acc[mt][nt][q] = 0.f;

    issue(0);
    issue(1);

    const uint32_t aLane = (uint32_t)lane * 16;
    const uint32_t bLane = (uint32_t)lane * 8;

    uint32_t af[2][4][4], bf[2][4][2];

    auto ldfrags = [&](int buf, uint32_t so, int ak) {
        #pragma unroll
        for (int mt = 0; mt < 4; mt++) {
            uint32_t addr = so + ((uint32_t)(ak * 8 + wm * 4 + mt) << 9) + aLane;
            asm volatile("ld.shared.v4.b32 {%0,%1,%2,%3}, [%4];"
                         : "=r"(af[buf][mt][0]), "=r"(af[buf][mt][1]),
                           "=r"(af[buf][mt][2]), "=r"(af[buf][mt][3]) : "r"(addr));
        }
        #pragma unroll
        for (int nt = 0; nt < 4; nt++) {
            uint32_t addr = so + AKB + ((uint32_t)(ak * 16 + wn * 4 + nt) << 8) + bLane;
            asm volatile("ld.shared.v2.b32 {%0,%1}, [%2];"
                         : "=r"(bf[buf][nt][0]), "=r"(bf[buf][nt][1]) : "r"(addr));
        }
    };

    for (int kt = 0; kt < KT; kt++) {
        asm volatile("cp.async.wait_group 1;" ::: "memory");
        __syncthreads();
        if (kt + 2 < KT) issue(kt + 2);

        const uint32_t so = sb + (uint32_t)(kt % STAGES) * STAGE_B;
        ldfrags(0, so, 0);
        #pragma unroll
        for (int ak = 0; ak < 4; ak++) {
            if (ak < 3) ldfrags((ak + 1) & 1, so, ak + 1);
            const int cur = ak & 1;
            #pragma unroll
            for (int mt = 0; mt < 4; mt++)
                #pragma unroll
                for (int nt = 0; nt < 4; nt++)
                    asm volatile(
                        "mma.sync.aligned.m16n8k8.row.col.f32.tf32.tf32.f32 "
                        "{%0,%1,%2,%3}, {%4,%5,%6,%7}, {%8,%9}, {%0,%1,%2,%3};"
                        : "+f"(acc[mt][nt][0]), "+f"(acc[mt][nt][1]),
                          "+f"(acc[mt][nt][2]), "+f"(acc[mt][nt][3])
                        : "r"(af[cur][mt][0]), "r"(af[cur][mt][1]),
                          "r"(af[cur][mt][2]), "r"(af[cur][mt][3]),
                          "r"(bf[cur][nt][0]), "r"(bf[cur][nt][1]));
        }
    }

    // ---------------- fused epilogue ----------------
    const int orow0 = bm + wm * 64 + g;
    const int ocol0 = bn + wn * 32 + 2 * tg;

    #pragma unroll
    for (int mt = 0; mt < 4; mt++) {
        const int r0 = orow0 + mt * 16;
        const float xs0 = g_xsq[r0];
        const float xs1 = g_xsq[r0 + 8];
        float* orow_a = out + (size_t)r0 * NP;
        float* orow_b = out + (size_t)(r0 + 8) * NP;
        #pragma unroll
        for (int nt = 0; nt < 4; nt++) {
            const int c = ocol0 + nt * 8;
            const float p0 = g_psq[c];
            const float p1 = g_psq[c + 1];
            float d00 = fmaxf(fmaf(-2.f, acc[mt][nt][0], xs0 + p0), 0.f);
            float d01 = fmaxf(fmaf(-2.f, acc[mt][nt][1], xs0 + p1), 0.f);
            float d10 = fmaxf(fmaf(-2.f, acc[mt][nt][2], xs1 + p0), 0.f);
            float d11 = fmaxf(fmaf(-2.f, acc[mt][nt][3], xs1 + p1), 0.f);
            float2 v0 = make_float2(__expf(-0.5f * sqrtf(d00)), __expf(-0.5f * sqrtf(d01)));
            float2 v1 = make_float2(__expf(-0.5f * sqrtf(d10)), __expf(-0.5f * sqrtf(d11)));
            *reinterpret_cast<float2*>(orow_a + c) = v0;
            *reinterpret_cast<float2*>(orow_b + c) = v1;
        }
    }
}

// ---------------- launch ----------------
extern "C" void kernel_launch(void* const* d_in, const int* in_sizes, int n_in,
                              void* d_out, int out_size) {
    const float* x = (const float*)d_in[0];   // [8192, 256]
    const float* p = (const float*)d_in[1];   // [8192, 256]
    float* out = (float*)d_out;               // [8192, 8192]

    static bool configured = false;
    if (!configured) {
        cudaFuncSetAttribute(gauss_mma_kernel,
                             cudaFuncAttributeMaxDynamicSharedMemorySize, SMEM_BYTES);
        configured = true;
    }

    prep_kernel<<<NB + NP, 256>>>(x, p);

    dim3 grid(NP / BN, NB / BM);
    gauss_mma_kernel<<<grid, 256, SMEM_BYTES>>>(out);
}

// round 6
// speedup vs baseline: 3.2508x; 1.0937x over previous
#include <cuda_runtime.h>
#include <cstdint>

#define NB 8192
#define NP 8192
#define NF 256
#define BM 128
#define BN 128
#define BK 32
#define KT (NF / BK)        // 8 k-tiles
#define STAGES 3
#define AKB 16384           // bytes of one 128x32 fp32 block (A or B)
#define STAGE_B (2 * AKB)   // 32 KB per stage (A + B)
#define SMEM_BYTES (STAGES * STAGE_B)  // 96 KB

// ---------------- device scratch (allocation-free) ----------------
__device__ float g_xsq[NB];
__device__ float g_psq[NP];
// fragment-order permuted tf32 copies: [tile(64)][kblock(8)][16KB block]
__device__ __align__(1024) float g_Xr[(size_t)NB * NF];
__device__ __align__(1024) float g_Pr[(size_t)NP * NF];

__device__ __forceinline__ uint32_t smem_u32(const void* p) {
    uint32_t a;
    asm("{ .reg .u64 t; cvta.to.shared.u64 t, %1; cvt.u32.u64 %0, t; }" : "=r"(a) : "l"(p));
    return a;
}

// ---------------- prepass: tf32 round + permute + row norms ----------------
// A block (128 m x 32 k, 16KB): atom = 16 m x 8 k = 512B, idx = ak*8 + am (32 atoms)
//   lane=(rr&7)*4+(cc&3), q=(rr>>3)|((cc>>2)<<1), off = atom*512 + lane*16 + q*4
// B block (128 n x 32 k, 16KB): atom = 16 n x 8 k = 512B (two n8 subtiles paired),
//   idx = ak*8 + pn (32 atoms), pn = n>>4, sub = (n>>3)&1, nn = n&7
//   lane=nn*4+(cc&3), off = atom*512 + lane*16 + sub*8 + (cc>>2)*4
__global__ __launch_bounds__(256) void prep_kernel(const float* __restrict__ X,
                                                   const float* __restrict__ P) {
    int row = blockIdx.x;
    bool isP = row >= NB;
    int r = isP ? row - NB : row;
    int t = threadIdx.x;

    float v = (isP ? P : X)[(size_t)r * NF + t];
    uint32_t u;
    asm("cvt.rna.tf32.f32 %0, %1;" : "=r"(u) : "f"(v));

    int tile = r >> 7, rin = r & 127, kb = t >> 5, kin = t & 31;
    int ak = kin >> 3, cc = kin & 7;
    char* base = (char*)(isP ? g_Pr : g_Xr) + (((size_t)tile * 8 + kb) << 14);
    uint32_t off;
    if (!isP) {
        int am = rin >> 4, rr = rin & 15;
        off = ((uint32_t)(ak * 8 + am) << 9)
            + (uint32_t)((rr & 7) * 4 + (cc & 3)) * 16u
            + ((uint32_t)((rr >> 3) | ((cc >> 2) << 1)) << 2);
    } else {
        int pn = rin >> 4, sub = (rin >> 3) & 1, nn = rin & 7;
        off = ((uint32_t)(ak * 8 + pn) << 9)
            + (uint32_t)(nn * 4 + (cc & 3)) * 16u
            + (uint32_t)(sub * 8)
            + ((uint32_t)(cc >> 2) << 2);
    }
    *reinterpret_cast<float*>(base + off) = __uint_as_float(u);

    float s = v * v;
    #pragma unroll
    for (int o = 16; o > 0; o >>= 1) s += __shfl_xor_sync(0xffffffffu, s, o);
    __shared__ float red[8];
    if ((t & 31) == 0) red[t >> 5] = s;
    __syncthreads();
    if (t == 0) {
        float tot = 0.f;
        #pragma unroll
        for (int i = 0; i < 8; i++) tot += red[i];
        (isP ? g_psq : g_xsq)[r] = tot;
    }
}

// ---------------- main kernel ----------------
__global__ __launch_bounds__(256, 2) void gauss_mma_kernel(float* __restrict__ out) {
    extern __shared__ char sm[];
    const uint32_t sb = smem_u32(sm);

    // tile swizzle: groups of 64 tm x 16 tn for L2 reuse
    const int id = blockIdx.y * gridDim.x + blockIdx.x;
    const int tn = ((id >> 10) << 4) | (id & 15);
    const int tm = (id & 1023) >> 4;
    const int bm = tm * BM, bn = tn * BN;

    const int tid = threadIdx.x;
    const int w = tid >> 5, lane = tid & 31;
    const int wm = w & 1, wn = w >> 1;      // 2(M) x 4(N), warp tile 64x32
    const int g = lane >> 2, tg = lane & 3;

    const char* gA = (const char*)g_Xr + ((size_t)tm * 8 << 14);
    const char* gB = (const char*)g_Pr + ((size_t)tn * 8 << 14);

    auto issue = [&](int kt) {
        const uint32_t so = sb + (uint32_t)(kt % STAGES) * STAGE_B + (uint32_t)tid * 64;
        const char* a = gA + ((size_t)kt << 14) + tid * 64;
        const char* b = gB + ((size_t)kt << 14) + tid * 64;
        #pragma unroll
        for (int j = 0; j < 4; j++) {
            asm volatile("cp.async.cg.shared.global [%0], [%1], 16;" :: "r"(so + j * 16), "l"(a + j * 16));
            asm volatile("cp.async.cg.shared.global [%0], [%1], 16;" :: "r"(so + AKB + j * 16), "l"(b + j * 16));
        }
        asm volatile("cp.async.commit_group;" ::: "memory");
    };

    float acc[4][4][4];
    #pragma unroll
    for (int mt = 0; mt < 4; mt++)
        #pragma unroll
        for (int nt = 0; nt < 4; nt++)
            #pragma unroll
            for (int q = 0; q < 4; q++) acc[mt][nt][q] = 0.f;

    const uint32_t laneOff = (uint32_t)lane * 16;

    uint32_t af[2][4][4];     // [buf][mt][a0..a3]
    uint32_t bf[2][2][4];     // [buf][pair][b0 lo, b1 lo, b0 hi, b1 hi]

    auto ldfrags = [&](int buf, uint32_t so, int ak) {
        #pragma unroll
        for (int mt = 0; mt < 4; mt++) {
            uint32_t addr = so + ((uint32_t)(ak * 8 + wm * 4 + mt) << 9) + laneOff;
            asm volatile("ld.shared.v4.b32 {%0,%1,%2,%3}, [%4];"
                         : "=r"(af[buf][mt][0]), "=r"(af[buf][mt][1]),
                           "=r"(af[buf][mt][2]), "=r"(af[buf][mt][3]) : "r"(addr));
        }
        #pragma unroll
        for (int pp = 0; pp < 2; pp++) {
            uint32_t addr = so + AKB + ((uint32_t)(ak * 8 + wn * 2 + pp) << 9) + laneOff;
            asm volatile("ld.shared.v4.b32 {%0,%1,%2,%3}, [%4];"
                         : "=r"(bf[buf][pp][0]), "=r"(bf[buf][pp][1]),
                           "=r"(bf[buf][pp][2]), "=r"(bf[buf][pp][3]) : "r"(addr));
        }
    };

    // prologue: 2 stages in flight, stage 0 resident, ak0 frags in buf0
    issue(0);
    issue(1);
    asm volatile("cp.async.wait_group 1;" ::: "memory");
    __syncthreads();
    ldfrags(0, sb, 0);

    for (int kt = 0; kt < KT; kt++) {
        const uint32_t so = sb + (uint32_t)(kt % STAGES) * STAGE_B;
        #pragma unroll
        for (int ak = 0; ak < 4; ak++) {
            if (ak == 0) {
                if (kt + 2 < KT) issue(kt + 2);
            }
            if (ak < 3) {
                ldfrags((ak + 1) & 1, so, ak + 1);
            } else if (kt + 1 < KT) {
                // stage boundary BEFORE the last MMA block: barrier + next-stage
                // ak0 prefetch overlap the outstanding MMAs of this kt.
                if (kt + 2 < KT) {
                    asm volatile("cp.async.wait_group 1;" ::: "memory");
                } else {
                    asm volatile("cp.async.wait_group 0;" ::: "memory");
                }
                __syncthreads();
                ldfrags(0, sb + (uint32_t)((kt + 1) % STAGES) * STAGE_B, 0);
            }
            const int cur = ak & 1;
            #pragma unroll
            for (int mt = 0; mt < 4; mt++)
                #pragma unroll
                for (int nt = 0; nt < 4; nt++) {
                    const int pp = nt >> 1, s = (nt & 1) * 2;
                    asm volatile(
                        "mma.sync.aligned.m16n8k8.row.col.f32.tf32.tf32.f32 "
                        "{%0,%1,%2,%3}, {%4,%5,%6,%7}, {%8,%9}, {%0,%1,%2,%3};"
                        : "+f"(acc[mt][nt][0]), "+f"(acc[mt][nt][1]),
                          "+f"(acc[mt][nt][2]), "+f"(acc[mt][nt][3])
                        : "r"(af[cur][mt][0]), "r"(af[cur][mt][1]),
                          "r"(af[cur][mt][2]), "r"(af[cur][mt][3]),
                          "r"(bf[cur][pp][s]), "r"(bf[cur][pp][s + 1]));
                }
        }
    }

    // ---------------- fused epilogue ----------------
    const int orow0 = bm + wm * 64 + g;
    const int ocol0 = bn + wn * 32 + 2 * tg;

    #pragma unroll
    for (int mt = 0; mt < 4; mt++) {
        const int r0 = orow0 + mt * 16;
        const float xs0 = g_xsq[r0];
        const float xs1 = g_xsq[r0 + 8];
        float* orow_a = out + (size_t)r0 * NP;
        float* orow_b = out + (size_t)(r0 + 8) * NP;
        #pragma unroll
        for (int nt = 0; nt < 4; nt++) {
            const int c = ocol0 + nt * 8;
            const float p0 = g_psq[c];
            const float p1 = g_psq[c + 1];
            float d00 = fmaxf(fmaf(-2.f, acc[mt][nt][0], xs0 + p0), 1e-30f);
            float d01 = fmaxf(fmaf(-2.f, acc[mt][nt][1], xs0 + p1), 1e-30f);
            float d10 = fmaxf(fmaf(-2.f, acc[mt][nt][2], xs1 + p0), 1e-30f);
            float d11 = fmaxf(fmaf(-2.f, acc[mt][nt][3], xs1 + p1), 1e-30f);
            float2 v0 = make_float2(__expf(-0.5f * d00 * rsqrtf(d00)),
                                    __expf(-0.5f * d01 * rsqrtf(d01)));
            float2 v1 = make_float2(__expf(-0.5f * d10 * rsqrtf(d10)),
                                    __expf(-0.5f * d11 * rsqrtf(d11)));
            *reinterpret_cast<float2*>(orow_a + c) = v0;
            *reinterpret_cast<float2*>(orow_b + c) = v1;
        }
    }
}

// ---------------- launch ----------------
extern "C" void kernel_launch(void* const* d_in, const int* in_sizes, int n_in,
                              void* d_out, int out_size) {
    const float* x = (const float*)d_in[0];   // [8192, 256]
    const float* p = (const float*)d_in[1];   // [8192, 256]
    float* out = (float*)d_out;               // [8192, 8192]

    static bool configured = false;
    if (!configured) {
        cudaFuncSetAttribute(gauss_mma_kernel,
                             cudaFuncAttributeMaxDynamicSharedMemorySize, SMEM_BYTES);
        configured = true;
    }

    prep_kernel<<<NB + NP, 256>>>(x, p);

    dim3 grid(NP / BN, NB / BM);
    gauss_mma_kernel<<<grid, 256, SMEM_BYTES>>>(out);
}